// round 11
// baseline (speedup 1.0000x reference)
#include <cuda_runtime.h>
#include <cuda_bf16.h>
#include <math.h>
#include <stdint.h>

// Problem constants (B=16, S=8192, D=192, H=16, HD=12, W=2)
constexpr int Bsz  = 16;
constexpr int Sln  = 8192;
constexpr int Dm   = 192;
constexpr int Mtot = Bsz * Sln;            // 131072 token rows
constexpr int Hn   = 16;
constexpr float NEGF = -3.402823466e+38f;  // finfo(float32).min
constexpr float QSCALE = 0.28867513459481287f; // 1/sqrt(12)

// ---------------------------------------------------------------------------
// Scratch (device globals; no runtime allocation)
// ---------------------------------------------------------------------------
__device__ __nv_bfloat16 g_asp[(size_t)Mtot * 384];     // x split: [M, hi192|lo192]
__device__ float         g_qkv[(size_t)Mtot * 576];     // q|k|v fp32
__device__ __nv_bfloat16 g_attn_sp[(size_t)Mtot * 384]; // attn out split
__device__ __nv_bfloat16 g_wsp[4 * 2 * 192 * 192];      // [w][hi/lo][N*K]
__device__ float         g_bias[768];                   // bq|bk|bv|bo

// ---------------------------------------------------------------------------
__device__ __forceinline__ uint32_t smem_to_u32(const void* p) {
    uint32_t a;
    asm("{ .reg .u64 t; cvta.to.shared.u64 t, %1; cvt.u32.u64 %0, t; }"
        : "=r"(a) : "l"(p));
    return a;
}
__device__ __forceinline__ void cpasync16(uint32_t dst, const void* src) {
    asm volatile("cp.async.cg.shared.global [%0], [%1], 16;" :: "r"(dst), "l"(src));
}
#define CP_COMMIT() asm volatile("cp.async.commit_group;" ::: "memory")
#define CP_WAIT2()  asm volatile("cp.async.wait_group 2;" ::: "memory")

#define LDSM_X4(f, addr)                                                        \
    asm volatile("ldmatrix.sync.aligned.m8n8.x4.shared.b16 {%0,%1,%2,%3}, [%4];"\
        : "=r"((f)[0]), "=r"((f)[1]), "=r"((f)[2]), "=r"((f)[3]) : "r"(addr))

#define MMA16816(d, a, b0v, b1v)                                                \
    asm volatile("mma.sync.aligned.m16n8k16.row.col.f32.bf16.bf16.f32 "         \
        "{%0,%1,%2,%3}, {%4,%5,%6,%7}, {%8,%9}, {%0,%1,%2,%3};"                 \
        : "+f"((d)[0]), "+f"((d)[1]), "+f"((d)[2]), "+f"((d)[3])                \
        : "r"((a)[0]), "r"((a)[1]), "r"((a)[2]), "r"((a)[3]), "r"(b0v), "r"(b1v))

constexpr int ROWB   = 80;                // smem row stride bytes (64B data + pad)
constexpr int KSTEPS = 18;                // K=576 effective / 32
constexpr int NSTG   = 6;

// QKV kernel: CTA 128x96, 2 CTAs/SM
constexpr int Q_ASZ = 128 * ROWB;         // 10240
constexpr int Q_BSZ = 96 * ROWB;          // 7680
constexpr int Q_STG = Q_ASZ + Q_BSZ;      // 17920
constexpr int SMEM_QKV = NSTG * Q_STG;    // 107520 (x2 CTAs = 215K <= 228K)

// O kernel: CTA 128x192, 512 threads, 1 CTA/SM
constexpr int O_ASZ = 128 * ROWB;         // 10240
constexpr int O_BSZ = 192 * ROWB;         // 15360
constexpr int O_STG = O_ASZ + O_BSZ;      // 25600
constexpr int SMEM_O = NSTG * O_STG;      // 153600

// ---------------------------------------------------------------------------
// Split x (fp32) -> [M, hi192 | lo192] bf16
// ---------------------------------------------------------------------------
__global__ void split_x(const float* __restrict__ x, __nv_bfloat16* __restrict__ dst) {
    const int id = blockIdx.x * blockDim.x + threadIdx.x;   // over M*48
    if (id >= Mtot * 48) return;
    const int m = id / 48, c = (id - m * 48) * 4;
    const float4 v = *(const float4*)(x + (size_t)m * 192 + c);
    __nv_bfloat16 h[4], l[4];
    const float vv[4] = {v.x, v.y, v.z, v.w};
    #pragma unroll
    for (int j = 0; j < 4; j++) {
        h[j] = __float2bfloat16_rn(vv[j]);
        l[j] = __float2bfloat16_rn(vv[j] - __bfloat162float(h[j]));
    }
    __nv_bfloat16* row = dst + (size_t)m * 384;
    *(__nv_bfloat162*)(row + c)       = __nv_bfloat162(h[0], h[1]);
    *(__nv_bfloat162*)(row + c + 2)   = __nv_bfloat162(h[2], h[3]);
    *(__nv_bfloat162*)(row + 192 + c) = __nv_bfloat162(l[0], l[1]);
    *(__nv_bfloat162*)(row + 194 + c) = __nv_bfloat162(l[2], l[3]);
}

// ---------------------------------------------------------------------------
// Split 4 weight matrices (Wq pre-scaled by 1/sqrt(HD)) + gather biases
// ---------------------------------------------------------------------------
__global__ void split_wb(const float* __restrict__ Wq, const float* __restrict__ Wk,
                         const float* __restrict__ Wv, const float* __restrict__ Wo,
                         const float* __restrict__ bq, const float* __restrict__ bk,
                         const float* __restrict__ bv, const float* __restrict__ bo) {
    const int id = blockIdx.x * blockDim.x + threadIdx.x;
    const int NW = 192 * 192;
    if (id < 4 * NW) {
        const int w = id / NW, e = id - w * NW;
        const float* src = (w == 0) ? Wq : (w == 1) ? Wk : (w == 2) ? Wv : Wo;
        float v = src[e];
        if (w == 0) v *= QSCALE;
        const __nv_bfloat16 h = __float2bfloat16_rn(v);
        g_wsp[(size_t)w * 2 * NW + e]      = h;
        g_wsp[(size_t)w * 2 * NW + NW + e] = __float2bfloat16_rn(v - __bfloat162float(h));
    } else {
        const int b = id - 4 * NW;
        if (b < 768) {
            const int w = b / 192, e = b - w * 192;
            const float bv_ = (w == 0) ? bq[e] * QSCALE
                           : (w == 1) ? bk[e] : (w == 2) ? bv[e] : bo[e];
            g_bias[b] = bv_;
        }
    }
}

// ---------------------------------------------------------------------------
// QKV GEMM: CTA 128x96, 256 threads (8 warps: 4M x 2N), 2 CTAs/SM.
// 6-stage ring, 2 k-chunks per barrier. grid = (6, Mtot/128).
// ---------------------------------------------------------------------------
__global__ void __launch_bounds__(256, 2) gemm_qkv(
    const __nv_bfloat16* __restrict__ Asp, float* __restrict__ out)
{
    extern __shared__ char smem[];
    const uint32_t sb = smem_to_u32(smem);
    const int tid  = threadIdx.x;
    const int wid  = tid >> 5, lane = tid & 31;
    const int wm   = wid >> 1;          // 0..3 (32-row band)
    const int wn   = wid & 1;           // 0..1 (48-col band)
    const int m0   = blockIdx.y * 128;
    const int w    = blockIdx.x >> 1;
    const int n0   = (blockIdx.x & 1) * 96;
    const __nv_bfloat16* whi = g_wsp + (size_t)w * 2 * 36864;
    const __nv_bfloat16* wlo = whi + 36864;

    auto issueStage = [&](int s, int stage) {
        const int seg = s / 6, kk = s - seg * 6;
        const __nv_bfloat16* wseg = (seg == 2) ? wlo : whi;
        const int colA = (seg == 1 ? 192 : 0) + kk * 32;
        const int colB = kk * 32;
        const uint32_t aBase = sb + stage * Q_STG;
        const uint32_t bBase = aBase + Q_ASZ;
        #pragma unroll
        for (int i = 0; i < 2; i++) {            // A: 128 rows x 4 chunks = 512
            const int id = tid + i * 256;
            const int r = id >> 2, c = id & 3;
            cpasync16(aBase + r * ROWB + c * 16,
                      Asp + (size_t)(m0 + r) * 384 + colA + c * 8);
        }
        {   // B: 96 rows x 4 chunks = 384
            const int r = tid >> 2, c = tid & 3;
            cpasync16(bBase + r * ROWB + c * 16,
                      wseg + (size_t)(n0 + r) * 192 + colB + c * 8);
            if (tid < 128) {
                const int id2 = tid + 256;
                const int r2 = id2 >> 2, c2 = id2 & 3;
                cpasync16(bBase + r2 * ROWB + c2 * 16,
                          wseg + (size_t)(n0 + r2) * 192 + colB + c2 * 8);
            }
        }
        CP_COMMIT();
    };

    float acc[2][6][4];
    #pragma unroll
    for (int i = 0; i < 2; i++)
        #pragma unroll
        for (int j = 0; j < 6; j++)
            #pragma unroll
            for (int q = 0; q < 4; q++) acc[i][j][q] = 0.f;

    issueStage(0, 0);
    issueStage(1, 1);
    issueStage(2, 2);
    issueStage(3, 3);

    const int lt = lane >> 3, l7 = lane & 7;
    const uint32_t aLane = (uint32_t)((wm * 32 + (lt & 1) * 8 + l7) * ROWB + (lt >> 1) * 16);
    const uint32_t bLane = (uint32_t)(Q_ASZ + (wn * 48 + (lt >> 1) * 8 + l7) * ROWB + (lt & 1) * 16);

    for (int p = 0; p < KSTEPS / 2; p++) {
        const int s = 2 * p;
        CP_WAIT2();
        __syncthreads();
        if (s + 4 < KSTEPS) issueStage(s + 4, (s + 4) % NSTG); else CP_COMMIT();
        if (s + 5 < KSTEPS) issueStage(s + 5, (s + 5) % NSTG); else CP_COMMIT();

        #pragma unroll
        for (int half = 0; half < 2; half++) {
            const uint32_t stBase = sb + ((s + half) % NSTG) * Q_STG;
            uint32_t af[2][2][4], bf[3][2][4];
            #pragma unroll
            for (int kh = 0; kh < 2; kh++) {
                #pragma unroll
                for (int mt = 0; mt < 2; mt++)
                    LDSM_X4(af[mt][kh], stBase + aLane + mt * (16 * ROWB) + kh * 32);
                #pragma unroll
                for (int nt2 = 0; nt2 < 3; nt2++)
                    LDSM_X4(bf[nt2][kh], stBase + bLane + nt2 * (16 * ROWB) + kh * 32);
            }
            #pragma unroll
            for (int kh = 0; kh < 2; kh++)
                #pragma unroll
                for (int mt = 0; mt < 2; mt++)
                    #pragma unroll
                    for (int nt = 0; nt < 6; nt++)
                        MMA16816(acc[mt][nt], af[mt][kh],
                                 bf[nt >> 1][kh][(nt & 1) * 2], bf[nt >> 1][kh][(nt & 1) * 2 + 1]);
        }
    }

    const int gi = lane >> 2, tg = lane & 3;
    const float* bias = g_bias + w * 192 + n0;
    #pragma unroll
    for (int mt = 0; mt < 2; mt++) {
        const int m = m0 + wm * 32 + mt * 16 + gi;
        #pragma unroll
        for (int nt = 0; nt < 6; nt++) {
            const int nb = wn * 48 + nt * 8 + tg * 2;
            const float2 bb = *(const float2*)(bias + nb);
            float2 v0, v1;
            v0.x = acc[mt][nt][0] + bb.x;  v0.y = acc[mt][nt][1] + bb.y;
            v1.x = acc[mt][nt][2] + bb.x;  v1.y = acc[mt][nt][3] + bb.y;
            *(float2*)(out + (size_t)m * 576 + w * 192 + n0 + nb)       = v0;
            *(float2*)(out + (size_t)(m + 8) * 576 + w * 192 + n0 + nb) = v1;
        }
    }
}

// ---------------------------------------------------------------------------
// O GEMM: CTA 128x192, 512 threads (16 warps: 4M x 4N), 6-stage ring,
// 2 k-chunks per barrier, fused bias+resid+LayerNorm.
// ---------------------------------------------------------------------------
__global__ void __launch_bounds__(512, 1) gemm_o(
    const __nv_bfloat16* __restrict__ Asp,
    const float* __restrict__ resid, float* __restrict__ out,
    const float* __restrict__ gamma, const float* __restrict__ beta)
{
    extern __shared__ char smem[];
    const uint32_t sb = smem_to_u32(smem);
    const int tid  = threadIdx.x;
    const int wid  = tid >> 5, lane = tid & 31;
    const int wm   = wid >> 2;          // 0..3 (32-row band)
    const int wn   = wid & 3;           // 0..3 (48-col band)
    const int m0   = blockIdx.x * 128;
    const __nv_bfloat16* whi = g_wsp + (size_t)3 * 2 * 36864;
    const __nv_bfloat16* wlo = whi + 36864;

    auto issueStage = [&](int s, int stage) {
        const int seg = s / 6, kk = s - seg * 6;
        const __nv_bfloat16* wseg = (seg == 2) ? wlo : whi;
        const int colA = (seg == 1 ? 192 : 0) + kk * 32;
        const int colB = kk * 32;
        const uint32_t aBase = sb + stage * O_STG;
        const uint32_t bBase = aBase + O_ASZ;
        {   // A: 128 rows x 4 chunks = 512
            const int r = tid >> 2, c = tid & 3;
            cpasync16(aBase + r * ROWB + c * 16,
                      Asp + (size_t)(m0 + r) * 384 + colA + c * 8);
        }
        {   // B: 192 rows x 4 chunks = 768
            const int r = tid >> 2, c = tid & 3;
            cpasync16(bBase + r * ROWB + c * 16,
                      wseg + (size_t)r * 192 + colB + c * 8);
            if (tid < 256) {
                const int id2 = tid + 512;
                const int r2 = id2 >> 2, c2 = id2 & 3;
                cpasync16(bBase + r2 * ROWB + c2 * 16,
                          wseg + (size_t)r2 * 192 + colB + c2 * 8);
            }
        }
        CP_COMMIT();
    };

    float acc[2][6][4];
    #pragma unroll
    for (int i = 0; i < 2; i++)
        #pragma unroll
        for (int j = 0; j < 6; j++)
            #pragma unroll
            for (int q = 0; q < 4; q++) acc[i][j][q] = 0.f;

    issueStage(0, 0);
    issueStage(1, 1);
    issueStage(2, 2);
    issueStage(3, 3);

    const int lt = lane >> 3, l7 = lane & 7;
    const uint32_t aLane = (uint32_t)((wm * 32 + (lt & 1) * 8 + l7) * ROWB + (lt >> 1) * 16);
    const uint32_t bLane = (uint32_t)(O_ASZ + (wn * 48 + (lt >> 1) * 8 + l7) * ROWB + (lt & 1) * 16);

    for (int p = 0; p < KSTEPS / 2; p++) {
        const int s = 2 * p;
        CP_WAIT2();
        __syncthreads();
        if (s + 4 < KSTEPS) issueStage(s + 4, (s + 4) % NSTG); else CP_COMMIT();
        if (s + 5 < KSTEPS) issueStage(s + 5, (s + 5) % NSTG); else CP_COMMIT();

        #pragma unroll
        for (int half = 0; half < 2; half++) {
            const uint32_t stBase = sb + ((s + half) % NSTG) * O_STG;
            uint32_t af[2][2][4], bf[3][2][4];
            #pragma unroll
            for (int kh = 0; kh < 2; kh++) {
                #pragma unroll
                for (int mt = 0; mt < 2; mt++)
                    LDSM_X4(af[mt][kh], stBase + aLane + mt * (16 * ROWB) + kh * 32);
                #pragma unroll
                for (int nt2 = 0; nt2 < 3; nt2++)
                    LDSM_X4(bf[nt2][kh], stBase + bLane + nt2 * (16 * ROWB) + kh * 32);
            }
            #pragma unroll
            for (int kh = 0; kh < 2; kh++)
                #pragma unroll
                for (int mt = 0; mt < 2; mt++)
                    #pragma unroll
                    for (int nt = 0; nt < 6; nt++)
                        MMA16816(acc[mt][nt], af[mt][kh],
                                 bf[nt >> 1][kh][(nt & 1) * 2], bf[nt >> 1][kh][(nt & 1) * 2 + 1]);
        }
    }

    const int gi = lane >> 2, tg = lane & 3;
    const float* bias = g_bias + 3 * 192;

    // bias + residual
    #pragma unroll
    for (int mt = 0; mt < 2; mt++) {
        const int mA = m0 + wm * 32 + mt * 16 + gi;
        #pragma unroll
        for (int nt = 0; nt < 6; nt++) {
            const int nb = wn * 48 + nt * 8 + tg * 2;
            const float2 bb = *(const float2*)(bias + nb);
            const float2 r0 = *(const float2*)(resid + (size_t)mA * 192 + nb);
            const float2 r1 = *(const float2*)(resid + (size_t)(mA + 8) * 192 + nb);
            acc[mt][nt][0] += bb.x + r0.x;  acc[mt][nt][1] += bb.y + r0.y;
            acc[mt][nt][2] += bb.x + r1.x;  acc[mt][nt][3] += bb.y + r1.y;
        }
    }
    // per-row partial sums across the 4 N-warps
    float* sums = (float*)smem;           // [128][4]
    float* sqs  = sums + 512;             // [128][4]
    __syncthreads();
    #pragma unroll
    for (int mt = 0; mt < 2; mt++) {
        float sA = 0.f, qA = 0.f, sB = 0.f, qB = 0.f;
        #pragma unroll
        for (int nt = 0; nt < 6; nt++) {
            sA += acc[mt][nt][0] + acc[mt][nt][1];
            qA += acc[mt][nt][0] * acc[mt][nt][0] + acc[mt][nt][1] * acc[mt][nt][1];
            sB += acc[mt][nt][2] + acc[mt][nt][3];
            qB += acc[mt][nt][2] * acc[mt][nt][2] + acc[mt][nt][3] * acc[mt][nt][3];
        }
        #pragma unroll
        for (int o = 1; o <= 2; o <<= 1) {
            sA += __shfl_xor_sync(0xffffffffu, sA, o);
            qA += __shfl_xor_sync(0xffffffffu, qA, o);
            sB += __shfl_xor_sync(0xffffffffu, sB, o);
            qB += __shfl_xor_sync(0xffffffffu, qB, o);
        }
        if (tg == 0) {
            const int rA = wm * 32 + mt * 16 + gi;
            sums[rA * 4 + wn] = sA;  sqs[rA * 4 + wn] = qA;
            sums[(rA + 8) * 4 + wn] = sB;  sqs[(rA + 8) * 4 + wn] = qB;
        }
    }
    __syncthreads();
    // normalize + write
    #pragma unroll
    for (int mt = 0; mt < 2; mt++) {
        const int rA = wm * 32 + mt * 16 + gi;
        const int mA = m0 + rA;
        const float sumA = sums[rA * 4] + sums[rA * 4 + 1] + sums[rA * 4 + 2] + sums[rA * 4 + 3];
        const float sqA  = sqs[rA * 4]  + sqs[rA * 4 + 1]  + sqs[rA * 4 + 2]  + sqs[rA * 4 + 3];
        const float sumB = sums[(rA + 8) * 4] + sums[(rA + 8) * 4 + 1] + sums[(rA + 8) * 4 + 2] + sums[(rA + 8) * 4 + 3];
        const float sqB  = sqs[(rA + 8) * 4]  + sqs[(rA + 8) * 4 + 1]  + sqs[(rA + 8) * 4 + 2]  + sqs[(rA + 8) * 4 + 3];
        const float muA = sumA * (1.f / 192.f);
        const float riA = rsqrtf(sqA * (1.f / 192.f) - muA * muA + 1e-12f);
        const float muB = sumB * (1.f / 192.f);
        const float riB = rsqrtf(sqB * (1.f / 192.f) - muB * muB + 1e-12f);
        #pragma unroll
        for (int nt = 0; nt < 6; nt++) {
            const int nb = wn * 48 + nt * 8 + tg * 2;
            const float2 gg = *(const float2*)(gamma + nb);
            const float2 be = *(const float2*)(beta + nb);
            float2 v0, v1;
            v0.x = (acc[mt][nt][0] - muA) * riA * gg.x + be.x;
            v0.y = (acc[mt][nt][1] - muA) * riA * gg.y + be.y;
            v1.x = (acc[mt][nt][2] - muB) * riB * gg.x + be.x;
            v1.y = (acc[mt][nt][3] - muB) * riB * gg.y + be.y;
            *(float2*)(out + (size_t)mA * 192 + nb)       = v0;
            *(float2*)(out + (size_t)(mA + 8) * 192 + nb) = v1;
        }
    }
}

// ---------------------------------------------------------------------------
// Banded attention (thread per token-head), output split to bf16 hi/lo
// ---------------------------------------------------------------------------
__global__ void attn_band(const float* __restrict__ qkv,
                          const float* __restrict__ mask0,
                          __nv_bfloat16* __restrict__ attn_sp)
{
    const int idx = blockIdx.x * blockDim.x + threadIdx.x;
    if (idx >= Mtot * Hn) return;
    const int m = idx >> 4;
    const int hh = idx & 15;
    const int s = m & (Sln - 1);

    const float4* qp = (const float4*)(qkv + (size_t)m * 576 + hh * 12);
    const float4 q0 = qp[0], q1 = qp[1], q2 = qp[2];

    float sc[5];
    #pragma unroll
    for (int d = 0; d < 5; d++) {
        const int off = d - 2;
        if ((unsigned)(s + off) < (unsigned)Sln) {
            const float4* kp = (const float4*)(qkv + (size_t)(m + off) * 576 + 192 + hh * 12);
            const float4 k0 = kp[0], k1 = kp[1], k2 = kp[2];
            float dot = q0.x * k0.x + q0.y * k0.y + q0.z * k0.z + q0.w * k0.w
                      + q1.x * k1.x + q1.y * k1.y + q1.z * k1.z + q1.w * k1.w
                      + q2.x * k2.x + q2.y * k2.y + q2.z * k2.z + q2.w * k2.w;
            sc[d] = dot + (mask0[m + off] != 0.f ? NEGF : 0.f);
        } else {
            sc[d] = -INFINITY;
        }
    }
    float mx = sc[0];
    #pragma unroll
    for (int d = 1; d < 5; d++) mx = fmaxf(mx, sc[d]);
    float e[5], sum = 0.f;
    #pragma unroll
    for (int d = 0; d < 5; d++) { e[d] = expf(sc[d] - mx); sum += e[d]; }
    const float inv = 1.f / sum;
    const bool zeroed = (mask0[m] < 0.f);

    float c[12];
    #pragma unroll
    for (int j = 0; j < 12; j++) c[j] = 0.f;
    #pragma unroll
    for (int d = 0; d < 5; d++) {
        const int off = d - 2;
        if ((unsigned)(s + off) < (unsigned)Sln) {
            const float p = zeroed ? 0.f : e[d] * inv;
            const float4* vp = (const float4*)(qkv + (size_t)(m + off) * 576 + 384 + hh * 12);
            const float4 v0 = vp[0], v1 = vp[1], v2 = vp[2];
            c[0] = fmaf(p, v0.x, c[0]); c[1]  = fmaf(p, v0.y, c[1]);
            c[2] = fmaf(p, v0.z, c[2]); c[3]  = fmaf(p, v0.w, c[3]);
            c[4] = fmaf(p, v1.x, c[4]); c[5]  = fmaf(p, v1.y, c[5]);
            c[6] = fmaf(p, v1.z, c[6]); c[7]  = fmaf(p, v1.w, c[7]);
            c[8] = fmaf(p, v2.x, c[8]); c[9]  = fmaf(p, v2.y, c[9]);
            c[10] = fmaf(p, v2.z, c[10]); c[11] = fmaf(p, v2.w, c[11]);
        }
    }
    __nv_bfloat16* hi = attn_sp + (size_t)m * 384 + hh * 12;
    __nv_bfloat16* lo = hi + 192;
    #pragma unroll
    for (int j = 0; j < 6; j++) {
        const __nv_bfloat16 h0 = __float2bfloat16_rn(c[2 * j]);
        const __nv_bfloat16 h1 = __float2bfloat16_rn(c[2 * j + 1]);
        *(__nv_bfloat162*)(hi + 2 * j) = __nv_bfloat162(h0, h1);
        *(__nv_bfloat162*)(lo + 2 * j) = __nv_bfloat162(
            __float2bfloat16_rn(c[2 * j]     - __bfloat162float(h0)),
            __float2bfloat16_rn(c[2 * j + 1] - __bfloat162float(h1)));
    }
}

// ---------------------------------------------------------------------------
extern "C" void kernel_launch(void* const* d_in, const int* in_sizes, int n_in,
                              void* d_out, int out_size)
{
    const float* x     = (const float*)d_in[0];
    const float* mask0 = (const float*)d_in[1];
    const float* Wq    = (const float*)d_in[2];
    const float* bq    = (const float*)d_in[3];
    const float* Wk    = (const float*)d_in[4];
    const float* bk    = (const float*)d_in[5];
    const float* Wv    = (const float*)d_in[6];
    const float* bv    = (const float*)d_in[7];
    const float* Wo    = (const float*)d_in[8];
    const float* bo    = (const float*)d_in[9];
    const float* ln_g  = (const float*)d_in[10];
    const float* ln_b  = (const float*)d_in[11];
    float* out = (float*)d_out;

    __nv_bfloat16 *asp, *attn_sp;
    float *qkv;
    cudaGetSymbolAddress((void**)&asp, g_asp);
    cudaGetSymbolAddress((void**)&qkv, g_qkv);
    cudaGetSymbolAddress((void**)&attn_sp, g_attn_sp);

    cudaFuncSetAttribute(gemm_qkv, cudaFuncAttributeMaxDynamicSharedMemorySize, SMEM_QKV);
    cudaFuncSetAttribute(gemm_o,   cudaFuncAttributeMaxDynamicSharedMemorySize, SMEM_O);

    split_x<<<(Mtot * 48) / 256, 256>>>(x, asp);
    split_wb<<<(4 * 192 * 192 + 768 + 255) / 256, 256>>>(Wq, Wk, Wv, Wo, bq, bk, bv, bo);

    // QKV: grid.x = weight*2 + Nhalf (x-fastest shares A tile in L2)
    gemm_qkv<<<dim3(6, 1024), 256, SMEM_QKV>>>(asp, qkv);

    attn_band<<<(Mtot * Hn) / 256, 256>>>(qkv, mask0, attn_sp);

    // O projection + bias + residual + fused LayerNorm -> d_out
    gemm_o<<<1024, 512, SMEM_O>>>(attn_sp, x, out, ln_g, ln_b);
}

// round 14
// speedup vs baseline: 1.0845x; 1.0845x over previous
#include <cuda_runtime.h>
#include <cuda_bf16.h>
#include <math.h>
#include <stdint.h>

// Problem constants (B=16, S=8192, D=192, H=16, HD=12, W=2)
constexpr int Bsz  = 16;
constexpr int Sln  = 8192;
constexpr int Dm   = 192;
constexpr int Mtot = Bsz * Sln;            // 131072 token rows
constexpr int Hn   = 16;
constexpr float NEGF = -3.402823466e+38f;  // finfo(float32).min
constexpr float QSCALE = 0.28867513459481287f; // 1/sqrt(12)

// ---------------------------------------------------------------------------
// Scratch (device globals; no runtime allocation)
// ---------------------------------------------------------------------------
__device__ __nv_bfloat16 g_asp[(size_t)Mtot * 384];     // x split: [M, hi192|lo192]
__device__ float         g_qkv[(size_t)Mtot * 576];     // q|k|v fp32
__device__ __nv_bfloat16 g_attn_sp[(size_t)Mtot * 384]; // attn out split
__device__ __nv_bfloat16 g_wsp[4 * 2 * 192 * 192];      // [w][hi/lo][N*K]
__device__ float         g_bias[768];                   // bq|bk|bv|bo

// ---------------------------------------------------------------------------
__device__ __forceinline__ uint32_t smem_to_u32(const void* p) {
    uint32_t a;
    asm("{ .reg .u64 t; cvta.to.shared.u64 t, %1; cvt.u32.u64 %0, t; }"
        : "=r"(a) : "l"(p));
    return a;
}
__device__ __forceinline__ void cpasync16(uint32_t dst, const void* src) {
    asm volatile("cp.async.cg.shared.global [%0], [%1], 16;" :: "r"(dst), "l"(src));
}
#define CP_COMMIT() asm volatile("cp.async.commit_group;" ::: "memory")
#define CP_WAIT3()  asm volatile("cp.async.wait_group 3;" ::: "memory")

#define LDSM_X4(f, addr)                                                        \
    asm volatile("ldmatrix.sync.aligned.m8n8.x4.shared.b16 {%0,%1,%2,%3}, [%4];"\
        : "=r"((f)[0]), "=r"((f)[1]), "=r"((f)[2]), "=r"((f)[3]) : "r"(addr))

#define MMA16816(d, a, b0v, b1v)                                                \
    asm volatile("mma.sync.aligned.m16n8k16.row.col.f32.bf16.bf16.f32 "         \
        "{%0,%1,%2,%3}, {%4,%5,%6,%7}, {%8,%9}, {%0,%1,%2,%3};"                 \
        : "+f"((d)[0]), "+f"((d)[1]), "+f"((d)[2]), "+f"((d)[3])                \
        : "r"((a)[0]), "r"((a)[1]), "r"((a)[2]), "r"((a)[3]), "r"(b0v), "r"(b1v))

constexpr int ROWB   = 80;                // smem row stride bytes (64B data + pad)
constexpr int KSTEPS = 18;                // K=576 effective / 32
constexpr int NSTG   = 5;

// QKV kernel: CTA 128x96, 2 CTAs/SM
constexpr int Q_ASZ = 128 * ROWB;         // 10240
constexpr int Q_BSZ = 96 * ROWB;          // 7680
constexpr int Q_STG = Q_ASZ + Q_BSZ;      // 17920
constexpr int SMEM_QKV = NSTG * Q_STG;    // 89600 (x2 CTAs = 179K <= 228K)

// O kernel: CTA 128x192, 512 threads, 1 CTA/SM
constexpr int O_ASZ = 128 * ROWB;         // 10240
constexpr int O_BSZ = 192 * ROWB;         // 15360
constexpr int O_STG = O_ASZ + O_BSZ;      // 25600
constexpr int SMEM_O = NSTG * O_STG;      // 128000

// ---------------------------------------------------------------------------
// Split x (fp32) -> [M, hi192 | lo192] bf16
// ---------------------------------------------------------------------------
__global__ void split_x(const float* __restrict__ x, __nv_bfloat16* __restrict__ dst) {
    const int id = blockIdx.x * blockDim.x + threadIdx.x;   // over M*48
    if (id >= Mtot * 48) return;
    const int m = id / 48, c = (id - m * 48) * 4;
    const float4 v = *(const float4*)(x + (size_t)m * 192 + c);
    __nv_bfloat16 h[4], l[4];
    const float vv[4] = {v.x, v.y, v.z, v.w};
    #pragma unroll
    for (int j = 0; j < 4; j++) {
        h[j] = __float2bfloat16_rn(vv[j]);
        l[j] = __float2bfloat16_rn(vv[j] - __bfloat162float(h[j]));
    }
    __nv_bfloat16* row = dst + (size_t)m * 384;
    *(__nv_bfloat162*)(row + c)       = __nv_bfloat162(h[0], h[1]);
    *(__nv_bfloat162*)(row + c + 2)   = __nv_bfloat162(h[2], h[3]);
    *(__nv_bfloat162*)(row + 192 + c) = __nv_bfloat162(l[0], l[1]);
    *(__nv_bfloat162*)(row + 194 + c) = __nv_bfloat162(l[2], l[3]);
}

// ---------------------------------------------------------------------------
// Split 4 weight matrices (Wq pre-scaled by 1/sqrt(HD)) + gather biases
// ---------------------------------------------------------------------------
__global__ void split_wb(const float* __restrict__ Wq, const float* __restrict__ Wk,
                         const float* __restrict__ Wv, const float* __restrict__ Wo,
                         const float* __restrict__ bq, const float* __restrict__ bk,
                         const float* __restrict__ bv, const float* __restrict__ bo) {
    const int id = blockIdx.x * blockDim.x + threadIdx.x;
    const int NW = 192 * 192;
    if (id < 4 * NW) {
        const int w = id / NW, e = id - w * NW;
        const float* src = (w == 0) ? Wq : (w == 1) ? Wk : (w == 2) ? Wv : Wo;
        float v = src[e];
        if (w == 0) v *= QSCALE;
        const __nv_bfloat16 h = __float2bfloat16_rn(v);
        g_wsp[(size_t)w * 2 * NW + e]      = h;
        g_wsp[(size_t)w * 2 * NW + NW + e] = __float2bfloat16_rn(v - __bfloat162float(h));
    } else {
        const int b = id - 4 * NW;
        if (b < 768) {
            const int w = b / 192, e = b - w * 192;
            const float bv_ = (w == 0) ? bq[e] * QSCALE
                           : (w == 1) ? bk[e] : (w == 2) ? bv[e] : bo[e];
            g_bias[b] = bv_;
        }
    }
}

// ---------------------------------------------------------------------------
// QKV GEMM: CTA 128x96, 256 threads (8 warps: 4M x 2N), 2 CTAs/SM.
// 5-stage ring, 1 k-chunk per barrier (R5 structure + deeper prefetch).
// grid = (6, Mtot/128).
// ---------------------------------------------------------------------------
__global__ void __launch_bounds__(256, 2) gemm_qkv(
    const __nv_bfloat16* __restrict__ Asp, float* __restrict__ out)
{
    extern __shared__ char smem[];
    const uint32_t sb = smem_to_u32(smem);
    const int tid  = threadIdx.x;
    const int wid  = tid >> 5, lane = tid & 31;
    const int wm   = wid >> 1;          // 0..3 (32-row band)
    const int wn   = wid & 1;           // 0..1 (48-col band)
    const int m0   = blockIdx.y * 128;
    const int w    = blockIdx.x >> 1;
    const int n0   = (blockIdx.x & 1) * 96;
    const __nv_bfloat16* whi = g_wsp + (size_t)w * 2 * 36864;
    const __nv_bfloat16* wlo = whi + 36864;

    auto issueStage = [&](int s, int stage) {
        const int seg = s / 6, kk = s - seg * 6;
        const __nv_bfloat16* wseg = (seg == 2) ? wlo : whi;
        const int colA = (seg == 1 ? 192 : 0) + kk * 32;
        const int colB = kk * 32;
        const uint32_t aBase = sb + stage * Q_STG;
        const uint32_t bBase = aBase + Q_ASZ;
        #pragma unroll
        for (int i = 0; i < 2; i++) {            // A: 128 rows x 4 chunks = 512
            const int id = tid + i * 256;
            const int r = id >> 2, c = id & 3;
            cpasync16(aBase + r * ROWB + c * 16,
                      Asp + (size_t)(m0 + r) * 384 + colA + c * 8);
        }
        {   // B: 96 rows x 4 chunks = 384
            const int r = tid >> 2, c = tid & 3;
            cpasync16(bBase + r * ROWB + c * 16,
                      wseg + (size_t)(n0 + r) * 192 + colB + c * 8);
            if (tid < 128) {
                const int id2 = tid + 256;
                const int r2 = id2 >> 2, c2 = id2 & 3;
                cpasync16(bBase + r2 * ROWB + c2 * 16,
                          wseg + (size_t)(n0 + r2) * 192 + colB + c2 * 8);
            }
        }
        CP_COMMIT();
    };

    float acc[2][6][4];
    #pragma unroll
    for (int i = 0; i < 2; i++)
        #pragma unroll
        for (int j = 0; j < 6; j++)
            #pragma unroll
            for (int q = 0; q < 4; q++) acc[i][j][q] = 0.f;

    issueStage(0, 0);
    issueStage(1, 1);
    issueStage(2, 2);
    issueStage(3, 3);

    const int lt = lane >> 3, l7 = lane & 7;
    const uint32_t aLane = (uint32_t)((wm * 32 + (lt & 1) * 8 + l7) * ROWB + (lt >> 1) * 16);
    const uint32_t bLane = (uint32_t)(Q_ASZ + (wn * 48 + (lt >> 1) * 8 + l7) * ROWB + (lt & 1) * 16);

    for (int s = 0; s < KSTEPS; s++) {
        const int stage = s % NSTG;
        CP_WAIT3();
        __syncthreads();
        if (s + 4 < KSTEPS) issueStage(s + 4, (s + 4) % NSTG);
        else CP_COMMIT();   // keep group count aligned so wait_group 3 => stage s arrived

        const uint32_t stBase = sb + stage * Q_STG;
        uint32_t af[2][2][4], bf[3][2][4];
        #pragma unroll
        for (int kh = 0; kh < 2; kh++) {
            #pragma unroll
            for (int mt = 0; mt < 2; mt++)
                LDSM_X4(af[mt][kh], stBase + aLane + mt * (16 * ROWB) + kh * 32);
            #pragma unroll
            for (int nt2 = 0; nt2 < 3; nt2++)
                LDSM_X4(bf[nt2][kh], stBase + bLane + nt2 * (16 * ROWB) + kh * 32);
        }
        #pragma unroll
        for (int kh = 0; kh < 2; kh++)
            #pragma unroll
            for (int mt = 0; mt < 2; mt++)
                #pragma unroll
                for (int nt = 0; nt < 6; nt++)
                    MMA16816(acc[mt][nt], af[mt][kh],
                             bf[nt >> 1][kh][(nt & 1) * 2], bf[nt >> 1][kh][(nt & 1) * 2 + 1]);
    }

    const int gi = lane >> 2, tg = lane & 3;
    const float* bias = g_bias + w * 192 + n0;
    #pragma unroll
    for (int mt = 0; mt < 2; mt++) {
        const int m = m0 + wm * 32 + mt * 16 + gi;
        #pragma unroll
        for (int nt = 0; nt < 6; nt++) {
            const int nb = wn * 48 + nt * 8 + tg * 2;
            const float2 bb = *(const float2*)(bias + nb);
            float2 v0, v1;
            v0.x = acc[mt][nt][0] + bb.x;  v0.y = acc[mt][nt][1] + bb.y;
            v1.x = acc[mt][nt][2] + bb.x;  v1.y = acc[mt][nt][3] + bb.y;
            *(float2*)(out + (size_t)m * 576 + w * 192 + n0 + nb)       = v0;
            *(float2*)(out + (size_t)(m + 8) * 576 + w * 192 + n0 + nb) = v1;
        }
    }
}

// ---------------------------------------------------------------------------
// O GEMM: CTA 128x192, 512 threads (16 warps: 4M x 4N), 5-stage ring,
// 1 k-chunk per barrier, fused bias+resid+LayerNorm.
// ---------------------------------------------------------------------------
__global__ void __launch_bounds__(512, 1) gemm_o(
    const __nv_bfloat16* __restrict__ Asp,
    const float* __restrict__ resid, float* __restrict__ out,
    const float* __restrict__ gamma, const float* __restrict__ beta)
{
    extern __shared__ char smem[];
    const uint32_t sb = smem_to_u32(smem);
    const int tid  = threadIdx.x;
    const int wid  = tid >> 5, lane = tid & 31;
    const int wm   = wid >> 2;          // 0..3 (32-row band)
    const int wn   = wid & 3;           // 0..3 (48-col band)
    const int m0   = blockIdx.x * 128;
    const __nv_bfloat16* whi = g_wsp + (size_t)3 * 2 * 36864;
    const __nv_bfloat16* wlo = whi + 36864;

    auto issueStage = [&](int s, int stage) {
        const int seg = s / 6, kk = s - seg * 6;
        const __nv_bfloat16* wseg = (seg == 2) ? wlo : whi;
        const int colA = (seg == 1 ? 192 : 0) + kk * 32;
        const int colB = kk * 32;
        const uint32_t aBase = sb + stage * O_STG;
        const uint32_t bBase = aBase + O_ASZ;
        {   // A: 128 rows x 4 chunks = 512
            const int r = tid >> 2, c = tid & 3;
            cpasync16(aBase + r * ROWB + c * 16,
                      Asp + (size_t)(m0 + r) * 384 + colA + c * 8);
        }
        {   // B: 192 rows x 4 chunks = 768
            const int r = tid >> 2, c = tid & 3;
            cpasync16(bBase + r * ROWB + c * 16,
                      wseg + (size_t)r * 192 + colB + c * 8);
            if (tid < 256) {
                const int id2 = tid + 512;
                const int r2 = id2 >> 2, c2 = id2 & 3;
                cpasync16(bBase + r2 * ROWB + c2 * 16,
                          wseg + (size_t)r2 * 192 + colB + c2 * 8);
            }
        }
        CP_COMMIT();
    };

    float acc[2][6][4];
    #pragma unroll
    for (int i = 0; i < 2; i++)
        #pragma unroll
        for (int j = 0; j < 6; j++)
            #pragma unroll
            for (int q = 0; q < 4; q++) acc[i][j][q] = 0.f;

    issueStage(0, 0);
    issueStage(1, 1);
    issueStage(2, 2);
    issueStage(3, 3);

    const int lt = lane >> 3, l7 = lane & 7;
    const uint32_t aLane = (uint32_t)((wm * 32 + (lt & 1) * 8 + l7) * ROWB + (lt >> 1) * 16);
    const uint32_t bLane = (uint32_t)(O_ASZ + (wn * 48 + (lt >> 1) * 8 + l7) * ROWB + (lt & 1) * 16);

    for (int s = 0; s < KSTEPS; s++) {
        const int stage = s % NSTG;
        CP_WAIT3();
        __syncthreads();
        if (s + 4 < KSTEPS) issueStage(s + 4, (s + 4) % NSTG);
        else CP_COMMIT();

        const uint32_t stBase = sb + stage * O_STG;
        uint32_t af[2][2][4], bf[3][2][4];
        #pragma unroll
        for (int kh = 0; kh < 2; kh++) {
            #pragma unroll
            for (int mt = 0; mt < 2; mt++)
                LDSM_X4(af[mt][kh], stBase + aLane + mt * (16 * ROWB) + kh * 32);
            #pragma unroll
            for (int nt2 = 0; nt2 < 3; nt2++)
                LDSM_X4(bf[nt2][kh], stBase + bLane + nt2 * (16 * ROWB) + kh * 32);
        }
        #pragma unroll
        for (int kh = 0; kh < 2; kh++)
            #pragma unroll
            for (int mt = 0; mt < 2; mt++)
                #pragma unroll
                for (int nt = 0; nt < 6; nt++)
                    MMA16816(acc[mt][nt], af[mt][kh],
                             bf[nt >> 1][kh][(nt & 1) * 2], bf[nt >> 1][kh][(nt & 1) * 2 + 1]);
    }

    const int gi = lane >> 2, tg = lane & 3;
    const float* bias = g_bias + 3 * 192;

    // bias + residual
    #pragma unroll
    for (int mt = 0; mt < 2; mt++) {
        const int mA = m0 + wm * 32 + mt * 16 + gi;
        #pragma unroll
        for (int nt = 0; nt < 6; nt++) {
            const int nb = wn * 48 + nt * 8 + tg * 2;
            const float2 bb = *(const float2*)(bias + nb);
            const float2 r0 = *(const float2*)(resid + (size_t)mA * 192 + nb);
            const float2 r1 = *(const float2*)(resid + (size_t)(mA + 8) * 192 + nb);
            acc[mt][nt][0] += bb.x + r0.x;  acc[mt][nt][1] += bb.y + r0.y;
            acc[mt][nt][2] += bb.x + r1.x;  acc[mt][nt][3] += bb.y + r1.y;
        }
    }
    // per-row partial sums across the 4 N-warps
    float* sums = (float*)smem;           // [128][4]
    float* sqs  = sums + 512;             // [128][4]
    __syncthreads();
    #pragma unroll
    for (int mt = 0; mt < 2; mt++) {
        float sA = 0.f, qA = 0.f, sB = 0.f, qB = 0.f;
        #pragma unroll
        for (int nt = 0; nt < 6; nt++) {
            sA += acc[mt][nt][0] + acc[mt][nt][1];
            qA += acc[mt][nt][0] * acc[mt][nt][0] + acc[mt][nt][1] * acc[mt][nt][1];
            sB += acc[mt][nt][2] + acc[mt][nt][3];
            qB += acc[mt][nt][2] * acc[mt][nt][2] + acc[mt][nt][3] * acc[mt][nt][3];
        }
        #pragma unroll
        for (int o = 1; o <= 2; o <<= 1) {
            sA += __shfl_xor_sync(0xffffffffu, sA, o);
            qA += __shfl_xor_sync(0xffffffffu, qA, o);
            sB += __shfl_xor_sync(0xffffffffu, sB, o);
            qB += __shfl_xor_sync(0xffffffffu, qB, o);
        }
        if (tg == 0) {
            const int rA = wm * 32 + mt * 16 + gi;
            sums[rA * 4 + wn] = sA;  sqs[rA * 4 + wn] = qA;
            sums[(rA + 8) * 4 + wn] = sB;  sqs[(rA + 8) * 4 + wn] = qB;
        }
    }
    __syncthreads();
    // normalize + write
    #pragma unroll
    for (int mt = 0; mt < 2; mt++) {
        const int rA = wm * 32 + mt * 16 + gi;
        const int mA = m0 + rA;
        const float sumA = sums[rA * 4] + sums[rA * 4 + 1] + sums[rA * 4 + 2] + sums[rA * 4 + 3];
        const float sqA  = sqs[rA * 4]  + sqs[rA * 4 + 1]  + sqs[rA * 4 + 2]  + sqs[rA * 4 + 3];
        const float sumB = sums[(rA + 8) * 4] + sums[(rA + 8) * 4 + 1] + sums[(rA + 8) * 4 + 2] + sums[(rA + 8) * 4 + 3];
        const float sqB  = sqs[(rA + 8) * 4]  + sqs[(rA + 8) * 4 + 1]  + sqs[(rA + 8) * 4 + 2]  + sqs[(rA + 8) * 4 + 3];
        const float muA = sumA * (1.f / 192.f);
        const float riA = rsqrtf(sqA * (1.f / 192.f) - muA * muA + 1e-12f);
        const float muB = sumB * (1.f / 192.f);
        const float riB = rsqrtf(sqB * (1.f / 192.f) - muB * muB + 1e-12f);
        #pragma unroll
        for (int nt = 0; nt < 6; nt++) {
            const int nb = wn * 48 + nt * 8 + tg * 2;
            const float2 gg = *(const float2*)(gamma + nb);
            const float2 be = *(const float2*)(beta + nb);
            float2 v0, v1;
            v0.x = (acc[mt][nt][0] - muA) * riA * gg.x + be.x;
            v0.y = (acc[mt][nt][1] - muA) * riA * gg.y + be.y;
            v1.x = (acc[mt][nt][2] - muB) * riB * gg.x + be.x;
            v1.y = (acc[mt][nt][3] - muB) * riB * gg.y + be.y;
            *(float2*)(out + (size_t)mA * 192 + nb)       = v0;
            *(float2*)(out + (size_t)(mA + 8) * 192 + nb) = v1;
        }
    }
}

// ---------------------------------------------------------------------------
// Banded attention (thread per token-head), output split to bf16 hi/lo
// ---------------------------------------------------------------------------
__global__ void attn_band(const float* __restrict__ qkv,
                          const float* __restrict__ mask0,
                          __nv_bfloat16* __restrict__ attn_sp)
{
    const int idx = blockIdx.x * blockDim.x + threadIdx.x;
    if (idx >= Mtot * Hn) return;
    const int m = idx >> 4;
    const int hh = idx & 15;
    const int s = m & (Sln - 1);

    const float4* qp = (const float4*)(qkv + (size_t)m * 576 + hh * 12);
    const float4 q0 = qp[0], q1 = qp[1], q2 = qp[2];

    float sc[5];
    #pragma unroll
    for (int d = 0; d < 5; d++) {
        const int off = d - 2;
        if ((unsigned)(s + off) < (unsigned)Sln) {
            const float4* kp = (const float4*)(qkv + (size_t)(m + off) * 576 + 192 + hh * 12);
            const float4 k0 = kp[0], k1 = kp[1], k2 = kp[2];
            float dot = q0.x * k0.x + q0.y * k0.y + q0.z * k0.z + q0.w * k0.w
                      + q1.x * k1.x + q1.y * k1.y + q1.z * k1.z + q1.w * k1.w
                      + q2.x * k2.x + q2.y * k2.y + q2.z * k2.z + q2.w * k2.w;
            sc[d] = dot + (mask0[m + off] != 0.f ? NEGF : 0.f);
        } else {
            sc[d] = -INFINITY;
        }
    }
    float mx = sc[0];
    #pragma unroll
    for (int d = 1; d < 5; d++) mx = fmaxf(mx, sc[d]);
    float e[5], sum = 0.f;
    #pragma unroll
    for (int d = 0; d < 5; d++) { e[d] = expf(sc[d] - mx); sum += e[d]; }
    const float inv = 1.f / sum;
    const bool zeroed = (mask0[m] < 0.f);

    float c[12];
    #pragma unroll
    for (int j = 0; j < 12; j++) c[j] = 0.f;
    #pragma unroll
    for (int d = 0; d < 5; d++) {
        const int off = d - 2;
        if ((unsigned)(s + off) < (unsigned)Sln) {
            const float p = zeroed ? 0.f : e[d] * inv;
            const float4* vp = (const float4*)(qkv + (size_t)(m + off) * 576 + 384 + hh * 12);
            const float4 v0 = vp[0], v1 = vp[1], v2 = vp[2];
            c[0] = fmaf(p, v0.x, c[0]); c[1]  = fmaf(p, v0.y, c[1]);
            c[2] = fmaf(p, v0.z, c[2]); c[3]  = fmaf(p, v0.w, c[3]);
            c[4] = fmaf(p, v1.x, c[4]); c[5]  = fmaf(p, v1.y, c[5]);
            c[6] = fmaf(p, v1.z, c[6]); c[7]  = fmaf(p, v1.w, c[7]);
            c[8] = fmaf(p, v2.x, c[8]); c[9]  = fmaf(p, v2.y, c[9]);
            c[10] = fmaf(p, v2.z, c[10]); c[11] = fmaf(p, v2.w, c[11]);
        }
    }
    __nv_bfloat16* hi = attn_sp + (size_t)m * 384 + hh * 12;
    __nv_bfloat16* lo = hi + 192;
    #pragma unroll
    for (int j = 0; j < 6; j++) {
        const __nv_bfloat16 h0 = __float2bfloat16_rn(c[2 * j]);
        const __nv_bfloat16 h1 = __float2bfloat16_rn(c[2 * j + 1]);
        *(__nv_bfloat162*)(hi + 2 * j) = __nv_bfloat162(h0, h1);
        *(__nv_bfloat162*)(lo + 2 * j) = __nv_bfloat162(
            __float2bfloat16_rn(c[2 * j]     - __bfloat162float(h0)),
            __float2bfloat16_rn(c[2 * j + 1] - __bfloat162float(h1)));
    }
}

// ---------------------------------------------------------------------------
extern "C" void kernel_launch(void* const* d_in, const int* in_sizes, int n_in,
                              void* d_out, int out_size)
{
    const float* x     = (const float*)d_in[0];
    const float* mask0 = (const float*)d_in[1];
    const float* Wq    = (const float*)d_in[2];
    const float* bq    = (const float*)d_in[3];
    const float* Wk    = (const float*)d_in[4];
    const float* bk    = (const float*)d_in[5];
    const float* Wv    = (const float*)d_in[6];
    const float* bv    = (const float*)d_in[7];
    const float* Wo    = (const float*)d_in[8];
    const float* bo    = (const float*)d_in[9];
    const float* ln_g  = (const float*)d_in[10];
    const float* ln_b  = (const float*)d_in[11];
    float* out = (float*)d_out;

    __nv_bfloat16 *asp, *attn_sp;
    float *qkv;
    cudaGetSymbolAddress((void**)&asp, g_asp);
    cudaGetSymbolAddress((void**)&qkv, g_qkv);
    cudaGetSymbolAddress((void**)&attn_sp, g_attn_sp);

    cudaFuncSetAttribute(gemm_qkv, cudaFuncAttributeMaxDynamicSharedMemorySize, SMEM_QKV);
    cudaFuncSetAttribute(gemm_o,   cudaFuncAttributeMaxDynamicSharedMemorySize, SMEM_O);

    split_x<<<(Mtot * 48) / 256, 256>>>(x, asp);
    split_wb<<<(4 * 192 * 192 + 768 + 255) / 256, 256>>>(Wq, Wk, Wv, Wo, bq, bk, bv, bo);

    // QKV: grid.x = weight*2 + Nhalf (x-fastest shares A tile in L2)
    gemm_qkv<<<dim3(6, 1024), 256, SMEM_QKV>>>(asp, qkv);

    attn_band<<<(Mtot * Hn) / 256, 256>>>(qkv, mask0, attn_sp);

    // O projection + bias + residual + fused LayerNorm -> d_out
    gemm_o<<<1024, 512, SMEM_O>>>(attn_sp, x, out, ln_g, ln_b);
}

// round 15
// speedup vs baseline: 1.1538x; 1.0638x over previous
#include <cuda_runtime.h>
#include <cuda_bf16.h>
#include <math.h>
#include <stdint.h>

// Problem constants (B=16, S=8192, D=192, H=16, HD=12, W=2)
constexpr int Bsz  = 16;
constexpr int Sln  = 8192;
constexpr int Dm   = 192;
constexpr int Mtot = Bsz * Sln;            // 131072 token rows
constexpr int Hn   = 16;
constexpr float NEGF = -3.402823466e+38f;  // finfo(float32).min
constexpr float QSCALE = 0.28867513459481287f; // 1/sqrt(12)

// ---------------------------------------------------------------------------
// Scratch (device globals; no runtime allocation)
// ---------------------------------------------------------------------------
__device__ __nv_bfloat16 g_asp[(size_t)Mtot * 384];     // x split: [M, hi192|lo192]
__device__ float         g_qkv[(size_t)Mtot * 576];     // q|k|v fp32
__device__ __nv_bfloat16 g_wsp[4 * 2 * 192 * 192];      // [w][hi/lo][N*K]
__device__ float         g_bias[768];                   // bq|bk|bv|bo

// ---------------------------------------------------------------------------
__device__ __forceinline__ uint32_t smem_to_u32(const void* p) {
    uint32_t a;
    asm("{ .reg .u64 t; cvta.to.shared.u64 t, %1; cvt.u32.u64 %0, t; }"
        : "=r"(a) : "l"(p));
    return a;
}
__device__ __forceinline__ void cpasync16(uint32_t dst, const void* src) {
    asm volatile("cp.async.cg.shared.global [%0], [%1], 16;" :: "r"(dst), "l"(src));
}
#define CP_COMMIT() asm volatile("cp.async.commit_group;" ::: "memory")
#define CP_WAIT2()  asm volatile("cp.async.wait_group 2;" ::: "memory")

#define LDSM_X4(f, addr)                                                        \
    asm volatile("ldmatrix.sync.aligned.m8n8.x4.shared.b16 {%0,%1,%2,%3}, [%4];"\
        : "=r"((f)[0]), "=r"((f)[1]), "=r"((f)[2]), "=r"((f)[3]) : "r"(addr))

#define MMA16816(d, a, b0v, b1v)                                                \
    asm volatile("mma.sync.aligned.m16n8k16.row.col.f32.bf16.bf16.f32 "         \
        "{%0,%1,%2,%3}, {%4,%5,%6,%7}, {%8,%9}, {%0,%1,%2,%3};"                 \
        : "+f"((d)[0]), "+f"((d)[1]), "+f"((d)[2]), "+f"((d)[3])                \
        : "r"((a)[0]), "r"((a)[1]), "r"((a)[2]), "r"((a)[3]), "r"(b0v), "r"(b1v))

constexpr int ROWB   = 80;                // stage smem row stride (64B data + pad)
constexpr int KSTEPS = 18;                // K=576 effective / 32
constexpr int NSTG   = 4;                 // exact R5 schedule

// QKV kernel: CTA 128x96, 2 CTAs/SM (exact R5 config)
constexpr int Q_ASZ = 128 * ROWB;         // 10240
constexpr int Q_BSZ = 96 * ROWB;          // 7680
constexpr int Q_STG = Q_ASZ + Q_BSZ;      // 17920
constexpr int SMEM_QKV = NSTG * Q_STG;    // 71680

// Fused O kernel: A resident (128 x 784B), B 4-stage ring
constexpr int A_ROWB  = 784;              // 392 bf16; 196 words => conflict-free LDSM
constexpr int OF_ABUF = 128 * A_ROWB;     // 100352
constexpr int OF_BSTG = 192 * ROWB;       // 15360 per stage
constexpr int SMEM_OF = OF_ABUF + NSTG * OF_BSTG;  // 161792

// ---------------------------------------------------------------------------
// Split x (fp32) -> [M, hi192 | lo192] bf16
// ---------------------------------------------------------------------------
__global__ void split_x(const float* __restrict__ x, __nv_bfloat16* __restrict__ dst) {
    const int id = blockIdx.x * blockDim.x + threadIdx.x;   // over M*48
    if (id >= Mtot * 48) return;
    const int m = id / 48, c = (id - m * 48) * 4;
    const float4 v = *(const float4*)(x + (size_t)m * 192 + c);
    __nv_bfloat16 h[4], l[4];
    const float vv[4] = {v.x, v.y, v.z, v.w};
    #pragma unroll
    for (int j = 0; j < 4; j++) {
        h[j] = __float2bfloat16_rn(vv[j]);
        l[j] = __float2bfloat16_rn(vv[j] - __bfloat162float(h[j]));
    }
    __nv_bfloat16* row = dst + (size_t)m * 384;
    *(__nv_bfloat162*)(row + c)       = __nv_bfloat162(h[0], h[1]);
    *(__nv_bfloat162*)(row + c + 2)   = __nv_bfloat162(h[2], h[3]);
    *(__nv_bfloat162*)(row + 192 + c) = __nv_bfloat162(l[0], l[1]);
    *(__nv_bfloat162*)(row + 194 + c) = __nv_bfloat162(l[2], l[3]);
}

// ---------------------------------------------------------------------------
// Split 4 weight matrices (Wq pre-scaled by 1/sqrt(HD)) + gather biases
// ---------------------------------------------------------------------------
__global__ void split_wb(const float* __restrict__ Wq, const float* __restrict__ Wk,
                         const float* __restrict__ Wv, const float* __restrict__ Wo,
                         const float* __restrict__ bq, const float* __restrict__ bk,
                         const float* __restrict__ bv, const float* __restrict__ bo) {
    const int id = blockIdx.x * blockDim.x + threadIdx.x;
    const int NW = 192 * 192;
    if (id < 4 * NW) {
        const int w = id / NW, e = id - w * NW;
        const float* src = (w == 0) ? Wq : (w == 1) ? Wk : (w == 2) ? Wv : Wo;
        float v = src[e];
        if (w == 0) v *= QSCALE;
        const __nv_bfloat16 h = __float2bfloat16_rn(v);
        g_wsp[(size_t)w * 2 * NW + e]      = h;
        g_wsp[(size_t)w * 2 * NW + NW + e] = __float2bfloat16_rn(v - __bfloat162float(h));
    } else {
        const int b = id - 4 * NW;
        if (b < 768) {
            const int w = b / 192, e = b - w * 192;
            const float bv_ = (w == 0) ? bq[e] * QSCALE
                           : (w == 1) ? bk[e] : (w == 2) ? bv[e] : bo[e];
            g_bias[b] = bv_;
        }
    }
}

// ---------------------------------------------------------------------------
// QKV GEMM: CTA 128x96, 256 threads (8 warps: 4M x 2N), 2 CTAs/SM.
// EXACT R5 schedule: 4-stage ring, 1 k-chunk per barrier, wait_group 2.
// grid = (6, Mtot/128).
// ---------------------------------------------------------------------------
__global__ void __launch_bounds__(256, 2) gemm_qkv(
    const __nv_bfloat16* __restrict__ Asp, float* __restrict__ out)
{
    extern __shared__ char smem[];
    const uint32_t sb = smem_to_u32(smem);
    const int tid  = threadIdx.x;
    const int wid  = tid >> 5, lane = tid & 31;
    const int wm   = wid >> 1;          // 0..3 (32-row band)
    const int wn   = wid & 1;           // 0..1 (48-col band)
    const int m0   = blockIdx.y * 128;
    const int w    = blockIdx.x >> 1;
    const int n0   = (blockIdx.x & 1) * 96;
    const __nv_bfloat16* whi = g_wsp + (size_t)w * 2 * 36864;
    const __nv_bfloat16* wlo = whi + 36864;

    auto issueStage = [&](int s, int stage) {
        const int seg = s / 6, kk = s - seg * 6;
        const __nv_bfloat16* wseg = (seg == 2) ? wlo : whi;
        const int colA = (seg == 1 ? 192 : 0) + kk * 32;
        const int colB = kk * 32;
        const uint32_t aBase = sb + stage * Q_STG;
        const uint32_t bBase = aBase + Q_ASZ;
        #pragma unroll
        for (int i = 0; i < 2; i++) {            // A: 128 rows x 4 chunks = 512
            const int id = tid + i * 256;
            const int r = id >> 2, c = id & 3;
            cpasync16(aBase + r * ROWB + c * 16,
                      Asp + (size_t)(m0 + r) * 384 + colA + c * 8);
        }
        {   // B: 96 rows x 4 chunks = 384
            const int r = tid >> 2, c = tid & 3;
            cpasync16(bBase + r * ROWB + c * 16,
                      wseg + (size_t)(n0 + r) * 192 + colB + c * 8);
            if (tid < 128) {
                const int id2 = tid + 256;
                const int r2 = id2 >> 2, c2 = id2 & 3;
                cpasync16(bBase + r2 * ROWB + c2 * 16,
                          wseg + (size_t)(n0 + r2) * 192 + colB + c2 * 8);
            }
        }
        CP_COMMIT();
    };

    float acc[2][6][4];
    #pragma unroll
    for (int i = 0; i < 2; i++)
        #pragma unroll
        for (int j = 0; j < 6; j++)
            #pragma unroll
            for (int q = 0; q < 4; q++) acc[i][j][q] = 0.f;

    issueStage(0, 0);
    issueStage(1, 1);
    issueStage(2, 2);

    const int lt = lane >> 3, l7 = lane & 7;
    const uint32_t aLane = (uint32_t)((wm * 32 + (lt & 1) * 8 + l7) * ROWB + (lt >> 1) * 16);
    const uint32_t bLane = (uint32_t)(Q_ASZ + (wn * 48 + (lt >> 1) * 8 + l7) * ROWB + (lt & 1) * 16);

    for (int s = 0; s < KSTEPS; s++) {
        const int stage = s & 3;
        CP_WAIT2();
        __syncthreads();
        if (s + 3 < KSTEPS) issueStage(s + 3, (s + 3) & 3);
        else CP_COMMIT();   // keep group count aligned

        const uint32_t stBase = sb + stage * Q_STG;
        uint32_t af[2][2][4], bf[3][2][4];
        #pragma unroll
        for (int kh = 0; kh < 2; kh++) {
            #pragma unroll
            for (int mt = 0; mt < 2; mt++)
                LDSM_X4(af[mt][kh], stBase + aLane + mt * (16 * ROWB) + kh * 32);
            #pragma unroll
            for (int nt2 = 0; nt2 < 3; nt2++)
                LDSM_X4(bf[nt2][kh], stBase + bLane + nt2 * (16 * ROWB) + kh * 32);
        }
        #pragma unroll
        for (int kh = 0; kh < 2; kh++)
            #pragma unroll
            for (int mt = 0; mt < 2; mt++)
                #pragma unroll
                for (int nt = 0; nt < 6; nt++)
                    MMA16816(acc[mt][nt], af[mt][kh],
                             bf[nt >> 1][kh][(nt & 1) * 2], bf[nt >> 1][kh][(nt & 1) * 2 + 1]);
    }

    const int gi = lane >> 2, tg = lane & 3;
    const float* bias = g_bias + w * 192 + n0;
    #pragma unroll
    for (int mt = 0; mt < 2; mt++) {
        const int m = m0 + wm * 32 + mt * 16 + gi;
        #pragma unroll
        for (int nt = 0; nt < 6; nt++) {
            const int nb = wn * 48 + nt * 8 + tg * 2;
            const float2 bb = *(const float2*)(bias + nb);
            float2 v0, v1;
            v0.x = acc[mt][nt][0] + bb.x;  v0.y = acc[mt][nt][1] + bb.y;
            v1.x = acc[mt][nt][2] + bb.x;  v1.y = acc[mt][nt][3] + bb.y;
            *(float2*)(out + (size_t)m * 576 + w * 192 + n0 + nb)       = v0;
            *(float2*)(out + (size_t)(m + 8) * 576 + w * 192 + n0 + nb) = v1;
        }
    }
}

// ---------------------------------------------------------------------------
// Fused O GEMM: banded attention computed in the prologue straight into the
// resident A-smem (bf16 hi/lo, GEMM layout), then 4-stage B-streamed GEMM
// with fused bias+resid+LayerNorm. CTA 128x192, 512 threads, grid = 1024.
// ---------------------------------------------------------------------------
__global__ void __launch_bounds__(512, 1) gemm_o_fused(
    const float* __restrict__ qkv, const float* __restrict__ mask0,
    const float* __restrict__ resid, float* __restrict__ out,
    const float* __restrict__ gamma, const float* __restrict__ beta)
{
    extern __shared__ char smem[];
    const uint32_t sb  = smem_to_u32(smem);
    const uint32_t sbB = sb + OF_ABUF;
    const int tid  = threadIdx.x;
    const int wid  = tid >> 5, lane = tid & 31;
    const int wm   = wid >> 2;          // 0..3 (32-row band)
    const int wn   = wid & 3;           // 0..3 (48-col band)
    const int m0   = blockIdx.x * 128;
    const __nv_bfloat16* whi = g_wsp + (size_t)3 * 2 * 36864;
    const __nv_bfloat16* wlo = whi + 36864;

    auto issueStage = [&](int s, int stage) {
        const int seg = s / 6, kk = s - seg * 6;
        const __nv_bfloat16* wseg = (seg == 2) ? wlo : whi;
        const int colB = kk * 32;
        const uint32_t bBase = sbB + stage * OF_BSTG;
        {   // B: 192 rows x 4 chunks = 768
            const int r = tid >> 2, c = tid & 3;
            cpasync16(bBase + r * ROWB + c * 16,
                      wseg + (size_t)r * 192 + colB + c * 8);
            if (tid < 256) {
                const int id2 = tid + 512;
                const int r2 = id2 >> 2, c2 = id2 & 3;
                cpasync16(bBase + r2 * ROWB + c2 * 16,
                          wseg + (size_t)r2 * 192 + colB + c2 * 8);
            }
        }
        CP_COMMIT();
    };

    // Prefetch first 3 B stages, then compute attention while they land.
    issueStage(0, 0);
    issueStage(1, 1);
    issueStage(2, 2);

    // ---- Prologue: banded attention for this CTA's 128 rows ----
    #pragma unroll
    for (int it = 0; it < 4; it++) {
        const int th  = it * 512 + tid;       // 0..2047
        const int r   = th >> 4;              // row 0..127
        const int hh  = th & 15;              // head
        const int m   = m0 + r;
        const int s   = m & (Sln - 1);

        const float4* qp = (const float4*)(qkv + (size_t)m * 576 + hh * 12);
        const float4 q0 = qp[0], q1 = qp[1], q2 = qp[2];

        float sc[5];
        #pragma unroll
        for (int d = 0; d < 5; d++) {
            const int off = d - 2;
            if ((unsigned)(s + off) < (unsigned)Sln) {
                const float4* kp = (const float4*)(qkv + (size_t)(m + off) * 576 + 192 + hh * 12);
                const float4 k0 = kp[0], k1 = kp[1], k2 = kp[2];
                float dot = q0.x * k0.x + q0.y * k0.y + q0.z * k0.z + q0.w * k0.w
                          + q1.x * k1.x + q1.y * k1.y + q1.z * k1.z + q1.w * k1.w
                          + q2.x * k2.x + q2.y * k2.y + q2.z * k2.z + q2.w * k2.w;
                sc[d] = dot + (mask0[m + off] != 0.f ? NEGF : 0.f);
            } else {
                sc[d] = -INFINITY;
            }
        }
        float mx = sc[0];
        #pragma unroll
        for (int d = 1; d < 5; d++) mx = fmaxf(mx, sc[d]);
        float e[5], sum = 0.f;
        #pragma unroll
        for (int d = 0; d < 5; d++) { e[d] = expf(sc[d] - mx); sum += e[d]; }
        const float inv = 1.f / sum;
        const bool zeroed = (mask0[m] < 0.f);

        float c[12];
        #pragma unroll
        for (int j = 0; j < 12; j++) c[j] = 0.f;
        #pragma unroll
        for (int d = 0; d < 5; d++) {
            const int off = d - 2;
            if ((unsigned)(s + off) < (unsigned)Sln) {
                const float p = zeroed ? 0.f : e[d] * inv;
                const float4* vp = (const float4*)(qkv + (size_t)(m + off) * 576 + 384 + hh * 12);
                const float4 v0 = vp[0], v1 = vp[1], v2 = vp[2];
                c[0] = fmaf(p, v0.x, c[0]); c[1]  = fmaf(p, v0.y, c[1]);
                c[2] = fmaf(p, v0.z, c[2]); c[3]  = fmaf(p, v0.w, c[3]);
                c[4] = fmaf(p, v1.x, c[4]); c[5]  = fmaf(p, v1.y, c[5]);
                c[6] = fmaf(p, v1.z, c[6]); c[7]  = fmaf(p, v1.w, c[7]);
                c[8] = fmaf(p, v2.x, c[8]); c[9]  = fmaf(p, v2.y, c[9]);
                c[10] = fmaf(p, v2.z, c[10]); c[11] = fmaf(p, v2.w, c[11]);
            }
        }
        // Store into resident A-smem: hi at col hh*12, lo at col 192 + hh*12
        char* rowp = smem + r * A_ROWB;
        __nv_bfloat162* hi = (__nv_bfloat162*)(rowp + hh * 24);
        __nv_bfloat162* lo = (__nv_bfloat162*)(rowp + 384 + hh * 24);
        #pragma unroll
        for (int j = 0; j < 6; j++) {
            const __nv_bfloat16 h0 = __float2bfloat16_rn(c[2 * j]);
            const __nv_bfloat16 h1 = __float2bfloat16_rn(c[2 * j + 1]);
            hi[j] = __nv_bfloat162(h0, h1);
            lo[j] = __nv_bfloat162(
                __float2bfloat16_rn(c[2 * j]     - __bfloat162float(h0)),
                __float2bfloat16_rn(c[2 * j + 1] - __bfloat162float(h1)));
        }
    }
    __syncthreads();   // A-smem fully built

    // ---- Mainloop (A resident, B streamed) ----
    float acc[2][6][4];
    #pragma unroll
    for (int i = 0; i < 2; i++)
        #pragma unroll
        for (int j = 0; j < 6; j++)
            #pragma unroll
            for (int q = 0; q < 4; q++) acc[i][j][q] = 0.f;

    const int lt = lane >> 3, l7 = lane & 7;
    const uint32_t aLane = (uint32_t)((wm * 32 + (lt & 1) * 8 + l7) * A_ROWB + (lt >> 1) * 16);
    const uint32_t bLane = (uint32_t)((wn * 48 + (lt >> 1) * 8 + l7) * ROWB + (lt & 1) * 16);

    for (int s = 0; s < KSTEPS; s++) {
        const int stage = s & 3;
        const int seg = s / 6, kk = s - seg * 6;
        const int colA = (seg == 1 ? 192 : 0) + kk * 32;
        CP_WAIT2();
        __syncthreads();
        if (s + 3 < KSTEPS) issueStage(s + 3, (s + 3) & 3);
        else CP_COMMIT();

        const uint32_t aBase = sb + (uint32_t)(colA * 2);
        const uint32_t bBase = sbB + stage * OF_BSTG;
        uint32_t af[2][2][4], bf[3][2][4];
        #pragma unroll
        for (int kh = 0; kh < 2; kh++) {
            #pragma unroll
            for (int mt = 0; mt < 2; mt++)
                LDSM_X4(af[mt][kh], aBase + aLane + mt * (16 * A_ROWB) + kh * 32);
            #pragma unroll
            for (int nt2 = 0; nt2 < 3; nt2++)
                LDSM_X4(bf[nt2][kh], bBase + bLane + nt2 * (16 * ROWB) + kh * 32);
        }
        #pragma unroll
        for (int kh = 0; kh < 2; kh++)
            #pragma unroll
            for (int mt = 0; mt < 2; mt++)
                #pragma unroll
                for (int nt = 0; nt < 6; nt++)
                    MMA16816(acc[mt][nt], af[mt][kh],
                             bf[nt >> 1][kh][(nt & 1) * 2], bf[nt >> 1][kh][(nt & 1) * 2 + 1]);
    }

    const int gi = lane >> 2, tg = lane & 3;
    const float* bias = g_bias + 3 * 192;

    // bias + residual
    #pragma unroll
    for (int mt = 0; mt < 2; mt++) {
        const int mA = m0 + wm * 32 + mt * 16 + gi;
        #pragma unroll
        for (int nt = 0; nt < 6; nt++) {
            const int nb = wn * 48 + nt * 8 + tg * 2;
            const float2 bb = *(const float2*)(bias + nb);
            const float2 r0 = *(const float2*)(resid + (size_t)mA * 192 + nb);
            const float2 r1 = *(const float2*)(resid + (size_t)(mA + 8) * 192 + nb);
            acc[mt][nt][0] += bb.x + r0.x;  acc[mt][nt][1] += bb.y + r0.y;
            acc[mt][nt][2] += bb.x + r1.x;  acc[mt][nt][3] += bb.y + r1.y;
        }
    }
    // per-row partial sums across the 4 N-warps (scratch overlays B ring)
    float* sums = (float*)(smem + OF_ABUF);   // [128][4]
    float* sqs  = sums + 512;                 // [128][4]
    __syncthreads();
    #pragma unroll
    for (int mt = 0; mt < 2; mt++) {
        float sA = 0.f, qA = 0.f, sB = 0.f, qB = 0.f;
        #pragma unroll
        for (int nt = 0; nt < 6; nt++) {
            sA += acc[mt][nt][0] + acc[mt][nt][1];
            qA += acc[mt][nt][0] * acc[mt][nt][0] + acc[mt][nt][1] * acc[mt][nt][1];
            sB += acc[mt][nt][2] + acc[mt][nt][3];
            qB += acc[mt][nt][2] * acc[mt][nt][2] + acc[mt][nt][3] * acc[mt][nt][3];
        }
        #pragma unroll
        for (int o = 1; o <= 2; o <<= 1) {
            sA += __shfl_xor_sync(0xffffffffu, sA, o);
            qA += __shfl_xor_sync(0xffffffffu, qA, o);
            sB += __shfl_xor_sync(0xffffffffu, sB, o);
            qB += __shfl_xor_sync(0xffffffffu, qB, o);
        }
        if (tg == 0) {
            const int rA = wm * 32 + mt * 16 + gi;
            sums[rA * 4 + wn] = sA;  sqs[rA * 4 + wn] = qA;
            sums[(rA + 8) * 4 + wn] = sB;  sqs[(rA + 8) * 4 + wn] = qB;
        }
    }
    __syncthreads();
    // normalize + write
    #pragma unroll
    for (int mt = 0; mt < 2; mt++) {
        const int rA = wm * 32 + mt * 16 + gi;
        const int mA = m0 + rA;
        const float sumA = sums[rA * 4] + sums[rA * 4 + 1] + sums[rA * 4 + 2] + sums[rA * 4 + 3];
        const float sqA  = sqs[rA * 4]  + sqs[rA * 4 + 1]  + sqs[rA * 4 + 2]  + sqs[rA * 4 + 3];
        const float sumB = sums[(rA + 8) * 4] + sums[(rA + 8) * 4 + 1] + sums[(rA + 8) * 4 + 2] + sums[(rA + 8) * 4 + 3];
        const float sqB  = sqs[(rA + 8) * 4]  + sqs[(rA + 8) * 4 + 1]  + sqs[(rA + 8) * 4 + 2]  + sqs[(rA + 8) * 4 + 3];
        const float muA = sumA * (1.f / 192.f);
        const float riA = rsqrtf(sqA * (1.f / 192.f) - muA * muA + 1e-12f);
        const float muB = sumB * (1.f / 192.f);
        const float riB = rsqrtf(sqB * (1.f / 192.f) - muB * muB + 1e-12f);
        #pragma unroll
        for (int nt = 0; nt < 6; nt++) {
            const int nb = wn * 48 + nt * 8 + tg * 2;
            const float2 gg = *(const float2*)(gamma + nb);
            const float2 be = *(const float2*)(beta + nb);
            float2 v0, v1;
            v0.x = (acc[mt][nt][0] - muA) * riA * gg.x + be.x;
            v0.y = (acc[mt][nt][1] - muA) * riA * gg.y + be.y;
            v1.x = (acc[mt][nt][2] - muB) * riB * gg.x + be.x;
            v1.y = (acc[mt][nt][3] - muB) * riB * gg.y + be.y;
            *(float2*)(out + (size_t)mA * 192 + nb)       = v0;
            *(float2*)(out + (size_t)(mA + 8) * 192 + nb) = v1;
        }
    }
}

// ---------------------------------------------------------------------------
extern "C" void kernel_launch(void* const* d_in, const int* in_sizes, int n_in,
                              void* d_out, int out_size)
{
    const float* x     = (const float*)d_in[0];
    const float* mask0 = (const float*)d_in[1];
    const float* Wq    = (const float*)d_in[2];
    const float* bq    = (const float*)d_in[3];
    const float* Wk    = (const float*)d_in[4];
    const float* bk    = (const float*)d_in[5];
    const float* Wv    = (const float*)d_in[6];
    const float* bv    = (const float*)d_in[7];
    const float* Wo    = (const float*)d_in[8];
    const float* bo    = (const float*)d_in[9];
    const float* ln_g  = (const float*)d_in[10];
    const float* ln_b  = (const float*)d_in[11];
    float* out = (float*)d_out;

    __nv_bfloat16 *asp;
    float *qkv;
    cudaGetSymbolAddress((void**)&asp, g_asp);
    cudaGetSymbolAddress((void**)&qkv, g_qkv);

    cudaFuncSetAttribute(gemm_qkv,    cudaFuncAttributeMaxDynamicSharedMemorySize, SMEM_QKV);
    cudaFuncSetAttribute(gemm_o_fused, cudaFuncAttributeMaxDynamicSharedMemorySize, SMEM_OF);

    split_x<<<(Mtot * 48) / 256, 256>>>(x, asp);
    split_wb<<<(4 * 192 * 192 + 768 + 255) / 256, 256>>>(Wq, Wk, Wv, Wo, bq, bk, bv, bo);

    // QKV: grid.x = weight*2 + Nhalf (x-fastest shares A tile in L2)
    gemm_qkv<<<dim3(6, 1024), 256, SMEM_QKV>>>(asp, qkv);

    // Fused: banded attention (prologue) + O projection + bias + residual + LN
    gemm_o_fused<<<1024, 512, SMEM_OF>>>(qkv, mask0, x, out, ln_g, ln_b);
}